// round 4
// baseline (speedup 1.0000x reference)
#include <cuda_runtime.h>

#define NN 8192
#define THREADS 256
#define NJ 32                      // j's per thread: 256*32 = 8192
#define GRID 444                   // 148 SMs * 3 CTAs -> exactly one wave
#define ROWS_MAX 19                // ceil(8192/444)

// Deterministic per-block partials + completion ticket.
__device__ float g_rank[GRID];
__device__ float g_cnt[GRID];
__device__ float g_reg[GRID];
__device__ unsigned int g_ticket;  // zero-initialized; reset by last block

__global__ void __launch_bounds__(THREADS)
svm_fused_kernel(const float* __restrict__ pred,
                 const float* __restrict__ target,
                 float* __restrict__ out)
{
    const int tid = threadIdx.x;
    const int bid = blockIdx.x;

    // Register-resident j data (loaded once, coalesced).
    float tj[NJ], pj[NJ];
    #pragma unroll
    for (int k = 0; k < NJ; ++k) {
        const int j = tid + k * THREADS;
        tj[k] = target[2 * j];     // time[j]
        pj[k] = pred[j];
    }

    // Preload ALL of this block's rows up front (high MLP, no exposed
    // per-row latency in the mainloop). ei = -1 marks an invalid row.
    float ti_r[ROWS_MAX], ei_r[ROWS_MAX], pi_r[ROWS_MAX];
    #pragma unroll
    for (int r = 0; r < ROWS_MAX; ++r) {
        const int i = bid + r * GRID;
        const bool v = (i < NN);
        const int ii = v ? i : 0;
        const float e = target[2 * ii + 1];
        ti_r[r] = target[2 * ii];
        pi_r[r] = pred[ii];
        ei_r[r] = v ? e : -1.0f;
    }

    float r0 = 0.f, r1 = 0.f, r2 = 0.f, r3 = 0.f;
    int   c0 = 0, c1 = 0;
    float reg_acc = 0.f;

    #pragma unroll
    for (int r = 0; r < ROWS_MAX; ++r) {
        const float ei = ei_r[r];
        if (ei < 0.f) continue;            // invalid (out-of-range) row
        const float ti = ti_r[r];
        const float pi = pi_r[r];

        if (tid == 0) {                    // regression term, once per row
            float d = pi - ti;
            if (ei == 0.f) d = fmaxf(d, 0.f);
            reg_acc = fmaf(d, d, reg_acc);
        }

        if (ei != 0.f) {                   // block-uniform branch
            const float c = 1.0f + pi;
            #pragma unroll
            for (int k = 0; k < NJ; k += 4) {
                { const bool m = tj[k]   > ti; const float h = fmaxf(c - pj[k],   0.f); if (m) { r0 = fmaf(h, h, r0); c0++; } }
                { const bool m = tj[k+1] > ti; const float h = fmaxf(c - pj[k+1], 0.f); if (m) { r1 = fmaf(h, h, r1); c1++; } }
                { const bool m = tj[k+2] > ti; const float h = fmaxf(c - pj[k+2], 0.f); if (m) { r2 = fmaf(h, h, r2); c0++; } }
                { const bool m = tj[k+3] > ti; const float h = fmaxf(c - pj[k+3], 0.f); if (m) { r3 = fmaf(h, h, r3); c1++; } }
            }
        }
    }

    const float rank_acc = (r0 + r1) + (r2 + r3);
    const int   cnt_acc  = c0 + c1;

    // Block reduction (shared tree, deterministic).
    __shared__ float red_r[THREADS];
    __shared__ float red_c[THREADS];
    __shared__ float red_g[THREADS];
    red_r[tid] = rank_acc;
    red_c[tid] = (float)cnt_acc;           // block sum < 2^24: exact in fp32
    red_g[tid] = reg_acc;
    __syncthreads();
    #pragma unroll
    for (int s = THREADS / 2; s > 0; s >>= 1) {
        if (tid < s) {
            red_r[tid] += red_r[tid + s];
            red_c[tid] += red_c[tid + s];
            red_g[tid] += red_g[tid + s];
        }
        __syncthreads();
    }

    // Publish partial, grab completion ticket.
    __shared__ bool s_last;
    if (tid == 0) {
        g_rank[bid] = red_r[0];
        g_cnt[bid]  = red_c[0];
        g_reg[bid]  = red_g[0];
        __threadfence();
        const unsigned int old = atomicAdd(&g_ticket, 1u);
        s_last = (old == GRID - 1);
    }
    __syncthreads();

    // Last block performs the deterministic final combine.
    if (s_last) {
        __threadfence();
        __shared__ double sr[THREADS];
        __shared__ double sc[THREADS];
        __shared__ double sg[THREADS];
        double rank = 0.0, cnt = 0.0, reg = 0.0;
        for (int b = tid; b < GRID; b += THREADS) {   // 2 iterations
            rank += (double)g_rank[b];
            cnt  += (double)g_cnt[b];
            reg  += (double)g_reg[b];
        }
        sr[tid] = rank; sc[tid] = cnt; sg[tid] = reg;
        __syncthreads();
        #pragma unroll
        for (int s = THREADS / 2; s > 0; s >>= 1) {
            if (tid < s) {
                sr[tid] += sr[tid + s];
                sc[tid] += sc[tid + s];
                sg[tid] += sg[tid + s];
            }
            __syncthreads();
        }
        if (tid == 0) {
            double c = sc[0];
            if (c < 1.0) c = 1.0;
            const double R = 0.5;
            const double loss = R * (sr[0] / c) + (1.0 - R) * (sg[0] / (double)NN);
            out[0] = (float)loss;
            g_ticket = 0;                 // reset for next graph replay
        }
    }
}

extern "C" void kernel_launch(void* const* d_in, const int* in_sizes, int n_in,
                              void* d_out, int out_size)
{
    // Robust input mapping: pred has NN elements, target has 2*NN.
    int pred_idx = 0, tgt_idx = 1;
    if (n_in >= 2 && in_sizes[0] > in_sizes[1]) { pred_idx = 1; tgt_idx = 0; }
    const float* pred   = (const float*)d_in[pred_idx];
    const float* target = (const float*)d_in[tgt_idx];
    float* out = (float*)d_out;

    svm_fused_kernel<<<GRID, THREADS>>>(pred, target, out);
}

// round 5
// speedup vs baseline: 1.1652x; 1.1652x over previous
#include <cuda_runtime.h>

#define NN 8192
#define THREADS 512
#define NJ 16                      // j's per thread: 512*16 = 8192
#define GRID 296                   // 148 SMs * 2 CTAs -> exactly one wave
#define ROWS_MAX 28                // ceil(8192/296) = 28

// Deterministic per-block partials + completion ticket.
__device__ float g_rank[GRID];
__device__ float g_cnt[GRID];
__device__ float g_reg[GRID];
__device__ unsigned int g_ticket;  // zero-initialized; reset by last block

__global__ void __launch_bounds__(THREADS, 2)
svm_fused_kernel(const float* __restrict__ pred,
                 const float* __restrict__ target,
                 float* __restrict__ out)
{
    const int tid = threadIdx.x;
    const int bid = blockIdx.x;

    // Register-resident j data (loaded once, coalesced). 32 registers.
    float tj[NJ], pj[NJ];
    #pragma unroll
    for (int k = 0; k < NJ; ++k) {
        const int j = tid + k * THREADS;
        tj[k] = target[2 * j];     // time[j]
        pj[k] = pred[j];
    }

    // This block's rows -> shared memory (no register cost).
    __shared__ float s_ti[ROWS_MAX];
    __shared__ float s_ei[ROWS_MAX];
    __shared__ float s_pi[ROWS_MAX];
    if (tid < ROWS_MAX) {
        const int i = bid + tid * GRID;
        const bool v = (i < NN);
        const int ii = v ? i : 0;
        s_ti[tid] = target[2 * ii];
        s_pi[tid] = pred[ii];
        s_ei[tid] = v ? target[2 * ii + 1] : -1.0f;  // -1 marks invalid
    }
    __syncthreads();

    float r0 = 0.f, r1 = 0.f, r2 = 0.f, r3 = 0.f;
    int   c0 = 0, c1 = 0;
    float reg_acc = 0.f;

    for (int r = 0; r < ROWS_MAX; ++r) {
        const float ei = s_ei[r];          // LDS broadcast
        if (ei < 0.f) continue;            // invalid row (uniform)
        const float ti = s_ti[r];
        const float pi = s_pi[r];

        if (tid == 0) {                    // regression term, once per row
            float d = pi - ti;
            if (ei == 0.f) d = fmaxf(d, 0.f);
            reg_acc = fmaf(d, d, reg_acc);
        }

        if (ei != 0.f) {                   // block-uniform branch
            const float c = 1.0f + pi;
            #pragma unroll
            for (int k = 0; k < NJ; k += 4) {
                { const bool m = tj[k]   > ti; const float h = fmaxf(c - pj[k],   0.f); if (m) { r0 = fmaf(h, h, r0); c0++; } }
                { const bool m = tj[k+1] > ti; const float h = fmaxf(c - pj[k+1], 0.f); if (m) { r1 = fmaf(h, h, r1); c1++; } }
                { const bool m = tj[k+2] > ti; const float h = fmaxf(c - pj[k+2], 0.f); if (m) { r2 = fmaf(h, h, r2); c0++; } }
                { const bool m = tj[k+3] > ti; const float h = fmaxf(c - pj[k+3], 0.f); if (m) { r3 = fmaf(h, h, r3); c1++; } }
            }
        }
    }

    const float rank_acc = (r0 + r1) + (r2 + r3);
    const int   cnt_acc  = c0 + c1;

    // Block reduction (shared tree, deterministic).
    __shared__ float red_r[THREADS];
    __shared__ float red_c[THREADS];
    __shared__ float red_g[THREADS];
    red_r[tid] = rank_acc;
    red_c[tid] = (float)cnt_acc;           // block sum < 2^24: exact in fp32
    red_g[tid] = reg_acc;
    __syncthreads();
    #pragma unroll
    for (int s = THREADS / 2; s > 0; s >>= 1) {
        if (tid < s) {
            red_r[tid] += red_r[tid + s];
            red_c[tid] += red_c[tid + s];
            red_g[tid] += red_g[tid + s];
        }
        __syncthreads();
    }

    // Publish partial, grab completion ticket.
    __shared__ bool s_last;
    if (tid == 0) {
        g_rank[bid] = red_r[0];
        g_cnt[bid]  = red_c[0];
        g_reg[bid]  = red_g[0];
        __threadfence();
        const unsigned int old = atomicAdd(&g_ticket, 1u);
        s_last = (old == GRID - 1);
    }
    __syncthreads();

    // Last block performs the deterministic final combine.
    if (s_last) {
        __threadfence();
        __shared__ double sr[THREADS];
        __shared__ double sc[THREADS];
        __shared__ double sg[THREADS];
        double rank = 0.0, cnt = 0.0, reg = 0.0;
        if (tid < GRID) {                  // 296 < 512: one element each
            rank = (double)g_rank[tid];
            cnt  = (double)g_cnt[tid];
            reg  = (double)g_reg[tid];
        }
        sr[tid] = rank; sc[tid] = cnt; sg[tid] = reg;
        __syncthreads();
        #pragma unroll
        for (int s = THREADS / 2; s > 0; s >>= 1) {
            if (tid < s) {
                sr[tid] += sr[tid + s];
                sc[tid] += sc[tid + s];
                sg[tid] += sg[tid + s];
            }
            __syncthreads();
        }
        if (tid == 0) {
            double c = sc[0];
            if (c < 1.0) c = 1.0;
            const double R = 0.5;
            const double loss = R * (sr[0] / c) + (1.0 - R) * (sg[0] / (double)NN);
            out[0] = (float)loss;
            g_ticket = 0;                 // reset for next graph replay
        }
    }
}

extern "C" void kernel_launch(void* const* d_in, const int* in_sizes, int n_in,
                              void* d_out, int out_size)
{
    // Robust input mapping: pred has NN elements, target has 2*NN.
    int pred_idx = 0, tgt_idx = 1;
    if (n_in >= 2 && in_sizes[0] > in_sizes[1]) { pred_idx = 1; tgt_idx = 0; }
    const float* pred   = (const float*)d_in[pred_idx];
    const float* target = (const float*)d_in[tgt_idx];
    float* out = (float*)d_out;

    svm_fused_kernel<<<GRID, THREADS>>>(pred, target, out);
}